// round 2
// baseline (speedup 1.0000x reference)
#include <cuda_runtime.h>

#define BATCH 16
#define NROW  196
#define CDIM  768
#define HDIM  512
#define ODIM  128
#define MTOT  (BATCH * NROW)   // 3136

#define TM 128
#define TN 64
#define TK 16
#define NTHREADS 128
#define MTILES ((MTOT + TM - 1) / TM)   // 25
#define NTILES (HDIM / TN)              // 8

// Scratch: s[which][b][h] = sum_i relu( x_which[b,i,:] . W_which[:,h] )
__device__ float g_s[2][BATCH][HDIM];

__global__ void zero_s_kernel() {
    int i = blockIdx.x * 256 + threadIdx.x;
    float* p = &g_s[0][0][0];
    if (i < 2 * BATCH * HDIM) p[i] = 0.0f;
}

// GEMM [3136,768] x [768,512] with ReLU + per-batch row-sum epilogue.
// blockIdx.z selects (x1,W1) vs (x2,W2).
__global__ __launch_bounds__(NTHREADS)
void gemm_relu_rowsum_kernel(const float* __restrict__ x1,
                             const float* __restrict__ x2,
                             const float* __restrict__ W1,
                             const float* __restrict__ W2) {
    const int which = blockIdx.z;
    const float* __restrict__ X = which ? x2 : x1;
    const float* __restrict__ W = which ? W2 : W1;

    const int m0 = blockIdx.x * TM;
    const int n0 = blockIdx.y * TN;
    const int tid = threadIdx.x;
    const int tr = tid >> 3;   // 0..15 : row group (8 rows each)
    const int tc = tid & 7;    // 0..7  : col group (8 cols each)

    __shared__ float Xs[TK][TM];   // transposed X tile: Xs[k][row]
    __shared__ float Ws[TK][TN];   // Ws[k][col]

    float acc[8][8];
#pragma unroll
    for (int i = 0; i < 8; i++)
#pragma unroll
        for (int j = 0; j < 8; j++) acc[i][j] = 0.0f;

    const int xrow = m0 + tid;            // each thread owns one X row per tile
    const bool xvalid = (xrow < MTOT);
    const float* xbase = X + (size_t)xrow * CDIM;

    // W load mapping: 1024 floats = 256 float4; thread loads idx = 2*tid + {0,1}
    const int widx0 = tid * 2;

    for (int k0 = 0; k0 < CDIM; k0 += TK) {
        // ---- global loads into registers ----
        float4 xv[4];
        if (xvalid) {
            const float4* src = (const float4*)(xbase + k0);
#pragma unroll
            for (int q = 0; q < 4; q++) xv[q] = src[q];
        } else {
#pragma unroll
            for (int q = 0; q < 4; q++) xv[q] = make_float4(0.f, 0.f, 0.f, 0.f);
        }
        float4 wv[2];
#pragma unroll
        for (int i = 0; i < 2; i++) {
            int idx = widx0 + i;
            int r = idx >> 4;          // k row within tile (0..15)
            int c4 = idx & 15;         // float4 index within 64 cols
            wv[i] = *(const float4*)(W + (size_t)(k0 + r) * HDIM + n0 + c4 * 4);
        }

        __syncthreads();   // previous tile's compute done

        // ---- store to smem ----
#pragma unroll
        for (int q = 0; q < 4; q++) {
            Xs[q * 4 + 0][tid] = xv[q].x;
            Xs[q * 4 + 1][tid] = xv[q].y;
            Xs[q * 4 + 2][tid] = xv[q].z;
            Xs[q * 4 + 3][tid] = xv[q].w;
        }
#pragma unroll
        for (int i = 0; i < 2; i++) {
            int idx = widx0 + i;
            int r = idx >> 4;
            int c4 = idx & 15;
            *(float4*)&Ws[r][c4 * 4] = wv[i];
        }

        __syncthreads();   // tile visible

        // ---- compute ----
#pragma unroll
        for (int kk = 0; kk < TK; kk++) {
            float xr[8], wc[8];
            *(float4*)&xr[0] = *(const float4*)&Xs[kk][tr * 8];
            *(float4*)&xr[4] = *(const float4*)&Xs[kk][tr * 8 + 4];
            *(float4*)&wc[0] = *(const float4*)&Ws[kk][tc * 8];
            *(float4*)&wc[4] = *(const float4*)&Ws[kk][tc * 8 + 4];
#pragma unroll
            for (int i = 0; i < 8; i++)
#pragma unroll
                for (int j = 0; j < 8; j++)
                    acc[i][j] = fmaf(xr[i], wc[j], acc[i][j]);
        }
    }

    // ---- epilogue: relu, group rows by batch, atomic into g_s ----
    const int rowbase = m0 + tr * 8;
    const int colbase = n0 + tc * 8;

    int i = 0;
    while (i < 8) {
        int gr = rowbase + i;
        if (gr >= MTOT) break;
        int b = gr / NROW;
        int bend = (b + 1) * NROW;   // exclusive global-row bound for this batch
        float cs[8];
#pragma unroll
        for (int j = 0; j < 8; j++) cs[j] = 0.0f;
        while (i < 8 && (rowbase + i) < bend && (rowbase + i) < MTOT) {
#pragma unroll
            for (int j = 0; j < 8; j++) cs[j] += fmaxf(acc[i][j], 0.0f);
            i++;
        }
        float* dst = &g_s[which][b][colbase];
#pragma unroll
        for (int j = 0; j < 8; j++) atomicAdd(dst + j, cs[j]);
    }
}

// out[b,o] = sum_h s1[b,h]*s2[b,h]*Wp[h,o] + bp[o]*N1*N2
__global__ __launch_bounds__(ODIM)
void final_kernel(const float* __restrict__ Wp,
                  const float* __restrict__ bp,
                  float* __restrict__ out) {
    const int b = blockIdx.x;
    const int o = threadIdx.x;

    __shared__ float sprod[HDIM];
    for (int h = o; h < HDIM; h += ODIM)
        sprod[h] = g_s[0][b][h] * g_s[1][b][h];
    __syncthreads();

    float acc = 0.0f;
#pragma unroll 8
    for (int h = 0; h < HDIM; h++)
        acc = fmaf(sprod[h], Wp[(size_t)h * ODIM + o], acc);

    out[b * ODIM + o] = acc + bp[o] * (float)(NROW * NROW);
}

extern "C" void kernel_launch(void* const* d_in, const int* in_sizes, int n_in,
                              void* d_out, int out_size) {
    const float* x1 = (const float*)d_in[0];
    const float* x2 = (const float*)d_in[1];
    const float* W1 = (const float*)d_in[2];
    const float* W2 = (const float*)d_in[3];
    const float* Wp = (const float*)d_in[4];
    const float* bp = (const float*)d_in[5];
    float* out = (float*)d_out;

    zero_s_kernel<<<(2 * BATCH * HDIM + 255) / 256, 256>>>();
    gemm_relu_rowsum_kernel<<<dim3(MTILES, NTILES, 2), NTHREADS>>>(x1, x2, W1, W2);
    final_kernel<<<BATCH, ODIM>>>(Wp, bp, out);
}